// round 15
// baseline (speedup 1.0000x reference)
#include <cuda_runtime.h>
#include <cuda_fp16.h>
#include <mma.h>

using namespace nvcuda;

#define N_POI  100000
#define N_EDGE 50000
#define NNZ    3200000
#define DD     128
#define SUB    8

#define SCAN_ELEMS 2048
#define NBLK_A ((N_EDGE + SCAN_ELEMS - 1) / SCAN_ELEMS)   // 25
#define NBLK_B ((N_POI  + SCAN_ELEMS - 1) / SCAN_ELEMS)   // 49

struct Pair { int c; float v; };

// ---------------- static scratch ----------------
__device__ float g_msg [(size_t)N_EDGE * DD];
__device__ float g_p1  [(size_t)N_POI * DD];
__device__ float g_e1  [(size_t)N_EDGE * DD];
__device__ float g_esum[(size_t)N_EDGE * DD];
__device__ __half g_ph    [(size_t)N_POI * DD];
__device__ __half g_fusedh[(size_t)N_EDGE * DD];
__device__ float g_Wcomb[DD * 256];

__device__ int  g_cntA[SUB * N_EDGE];
__device__ int  g_cntB[SUB * N_POI];
__device__ int  g_rpA [N_EDGE + 1];
__device__ int  g_rpB [N_POI + 1];
__device__ int  g_curA[SUB * N_EDGE];
__device__ int  g_curB[SUB * N_POI];
__device__ int  g_auxA[NBLK_A];
__device__ int  g_auxB[NBLK_B];
__device__ Pair g_pairsA[NNZ];
__device__ Pair g_pairsB[NNZ];

// ---------------- init: clear counters + poi fp32->fp16 (fused) ----------------
__global__ void init_kernel(int* __restrict__ cA, int nA, int* __restrict__ cB, int nB,
                            const float4* __restrict__ x, uint2* __restrict__ xh, int n4) {
    int total = nA + nB + n4;
    for (int i = blockIdx.x * blockDim.x + threadIdx.x; i < total; i += gridDim.x * blockDim.x) {
        if (i < nA) {
            cA[i] = 0;
        } else if (i < nA + nB) {
            cB[i - nA] = 0;
        } else {
            int k = i - nA - nB;
            float4 v = x[k];
            __half2 h0 = __floats2half2_rn(v.x, v.y);
            __half2 h1 = __floats2half2_rn(v.z, v.w);
            uint2 u;
            u.x = *(unsigned*)&h0;
            u.y = *(unsigned*)&h1;
            xh[k] = u;
        }
    }
}

// ---------------- CSR build ----------------
__global__ void __launch_bounds__(256) hist2_kernel(const int* __restrict__ rA, const int* __restrict__ rB,
                                                    int* __restrict__ cA, int* __restrict__ cB) {
    const int total = 2 * NNZ;
    const int S = gridDim.x * blockDim.x;
    int base = blockIdx.x * blockDim.x + threadIdx.x;
    int sub = base & (SUB - 1);
    for (; base < total; base += 4 * S) {
        int r[4]; bool m[4]; bool isA[4];
#pragma unroll
        for (int j = 0; j < 4; j++) {
            int i = base + j * S;
            m[j] = i < total;
            isA[j] = i < NNZ;
            if (m[j]) r[j] = isA[j] ? rA[i] : rB[i - NNZ];
        }
#pragma unroll
        for (int j = 0; j < 4; j++) {
            if (m[j]) {
                if (isA[j]) atomicAdd(&cA[r[j] * SUB + sub], 1);
                else        atomicAdd(&cB[r[j] * SUB + sub], 1);
            }
        }
    }
}

// row totals -> rp arrays (pre-scan)
__global__ void rowsum_kernel(const int4* __restrict__ cntA, const int4* __restrict__ cntB,
                              int* __restrict__ rpA, int* __restrict__ rpB) {
    const int total = N_EDGE + N_POI;
    for (int r = blockIdx.x * blockDim.x + threadIdx.x; r < total; r += gridDim.x * blockDim.x) {
        if (r < N_EDGE) {
            int4 a = cntA[r * 2], b = cntA[r * 2 + 1];
            rpA[r] = a.x + a.y + a.z + a.w + b.x + b.y + b.z + b.w;
        } else {
            int rr = r - N_EDGE;
            int4 a = cntB[rr * 2], b = cntB[rr * 2 + 1];
            rpB[rr] = a.x + a.y + a.z + a.w + b.x + b.y + b.z + b.w;
        }
    }
}

// Per-block exclusive scan of 2048 elements; block total into aux.
__global__ void __launch_bounds__(1024) scan_blocks_kernel(int* __restrict__ dA, int* __restrict__ auxA,
                                                           int* __restrict__ dB, int* __restrict__ auxB) {
    __shared__ int sh[1024];
    int blk = blockIdx.x;
    int* data; int* aux; int n; int b;
    if (blk < NBLK_A) { data = dA; aux = auxA; n = N_EDGE; b = blk; }
    else              { data = dB; aux = auxB; n = N_POI;  b = blk - NBLK_A; }
    int t = threadIdx.x;
    int i0 = b * SCAN_ELEMS + t * 2;
    int x0 = (i0     < n) ? data[i0]     : 0;
    int x1 = (i0 + 1 < n) ? data[i0 + 1] : 0;
    int s = x0 + x1;
    sh[t] = s;
    __syncthreads();
#pragma unroll
    for (int off = 1; off < 1024; off <<= 1) {
        int v  = sh[t];
        int vo = (t >= off) ? sh[t - off] : 0;
        __syncthreads();
        sh[t] = v + vo;
        __syncthreads();
    }
    int excl = sh[t] - s;
    if (i0     < n) data[i0]     = excl;
    if (i0 + 1 < n) data[i0 + 1] = excl + x0;
    if (t == 1023) aux[b] = sh[1023];
}

// One block: warp 0 scans auxA, warp 1 scans auxB; writes totals to rp[n].
__global__ void scan_aux_kernel(int* __restrict__ auxA, int* __restrict__ rpA,
                                int* __restrict__ auxB, int* __restrict__ rpB) {
    int w = threadIdx.x >> 5;
    int lane = threadIdx.x & 31;
    int* aux; int nblk; int* rpEnd;
    if (w == 0) { aux = auxA; nblk = NBLK_A; rpEnd = rpA + N_EDGE; }
    else        { aux = auxB; nblk = NBLK_B; rpEnd = rpB + N_POI; }
    int carry = 0;
    for (int c = 0; c < nblk; c += 32) {
        int idx = c + lane;
        int orig = (idx < nblk) ? aux[idx] : 0;
        int v = orig;
#pragma unroll
        for (int off = 1; off < 32; off <<= 1) {
            int tmp = __shfl_up_sync(0xFFFFFFFF, v, off);
            if (lane >= off) v += tmp;
        }
        if (idx < nblk) aux[idx] = v - orig + carry;
        carry += __shfl_sync(0xFFFFFFFF, v, 31);
    }
    if (lane == 0) *rpEnd = carry;
}

// cursors: absolute base per row; sub-bucket cursors.
__global__ void cursor_kernel(int* __restrict__ rpA, const int* __restrict__ auxA,
                              const int4* __restrict__ cntA, int4* __restrict__ curA,
                              int* __restrict__ rpB, const int* __restrict__ auxB,
                              const int4* __restrict__ cntB, int4* __restrict__ curB) {
    const int total = N_EDGE + N_POI;
    for (int r = blockIdx.x * blockDim.x + threadIdx.x; r < total; r += gridDim.x * blockDim.x) {
        const int4* cnt; int4* cur; int base; int rr;
        if (r < N_EDGE) {
            rr = r; cnt = cntA; cur = curA;
            base = rpA[rr] + auxA[rr >> 11];
            rpA[rr] = base;
        } else {
            rr = r - N_EDGE; cnt = cntB; cur = curB;
            base = rpB[rr] + auxB[rr >> 11];
            rpB[rr] = base;
        }
        int4 a = cnt[rr * 2], b = cnt[rr * 2 + 1];
        int4 oa, ob;
        oa.x = base;
        oa.y = oa.x + a.x;
        oa.z = oa.y + a.y;
        oa.w = oa.z + a.z;
        ob.x = oa.w + a.w;
        ob.y = ob.x + b.x;
        ob.z = ob.y + b.y;
        ob.w = ob.z + b.z;
        cur[rr * 2] = oa;
        cur[rr * 2 + 1] = ob;
    }
}

__global__ void __launch_bounds__(256) scatter2_kernel(const int* __restrict__ rA, const int* __restrict__ cAi,
                                                       const float* __restrict__ vAi, int* __restrict__ curA,
                                                       Pair* __restrict__ pA,
                                                       const int* __restrict__ rB, const int* __restrict__ cBi,
                                                       const float* __restrict__ vBi, int* __restrict__ curB,
                                                       Pair* __restrict__ pB) {
    const int total = 2 * NNZ;
    const int S = gridDim.x * blockDim.x;
    int base = blockIdx.x * blockDim.x + threadIdx.x;
    int sub = base & (SUB - 1);
    for (; base < total; base += 4 * S) {
        int r[4], c[4]; float v[4]; bool m[4], isA[4];
#pragma unroll
        for (int j = 0; j < 4; j++) {
            int i = base + j * S;
            m[j] = i < total;
            isA[j] = i < NNZ;
            if (m[j]) {
                if (isA[j]) { r[j] = rA[i]; c[j] = cAi[i]; v[j] = vAi[i]; }
                else        { int k = i - NNZ; r[j] = rB[k]; c[j] = cBi[k]; v[j] = vBi[k]; }
            }
        }
#pragma unroll
        for (int j = 0; j < 4; j++) {
            if (m[j]) {
                Pair pr; pr.c = c[j]; pr.v = v[j];
                if (isA[j]) { int pos = atomicAdd(&curA[r[j] * SUB + sub], 1); pA[pos] = pr; }
                else        { int pos = atomicAdd(&curB[r[j] * SUB + sub], 1); pB[pos] = pr; }
            }
        }
    }
}

// ---------------- weight folding ----------------
__global__ void wfold_kernel(const float* __restrict__ Wfus, const float* __restrict__ Wpoi,
                             const float* __restrict__ Wedge, float* __restrict__ Wcomb) {
    __shared__ float row[256];
    int j = blockIdx.x;
    int t = threadIdx.x;
    row[t] = Wfus[j * 256 + t];
    __syncthreads();
    float s = 0.f;
    if (t < 128) {
#pragma unroll 8
        for (int m = 0; m < 128; m++) s += row[m] * Wpoi[m * 128 + t];
    } else {
        int tt = t - 128;
#pragma unroll 8
        for (int k = 0; k < 128; k++) s += row[128 + k] * Wedge[k * 128 + tt];
    }
    Wcomb[j * 256 + t] = s;
}

// ---------------- SpMM core (fp16 gather) ----------------
__device__ __forceinline__ void spmm_row_acc_h(const Pair* __restrict__ prs,
                                               const uint2* __restrict__ xh,
                                               int s, int e, int lane,
                                               float& ax, float& ay, float& az, float& aw) {
    int j = s;
    for (; j + 4 <= e; j += 4) {
        Pair p0 = prs[j], p1 = prs[j + 1], p2 = prs[j + 2], p3 = prs[j + 3];
        uint2 g0 = xh[(size_t)p0.c * 32 + lane];
        uint2 g1 = xh[(size_t)p1.c * 32 + lane];
        uint2 g2 = xh[(size_t)p2.c * 32 + lane];
        uint2 g3 = xh[(size_t)p3.c * 32 + lane];
#pragma unroll
        for (int q = 0; q < 4; q++) {
            uint2 g = q == 0 ? g0 : q == 1 ? g1 : q == 2 ? g2 : g3;
            float v = q == 0 ? p0.v : q == 1 ? p1.v : q == 2 ? p2.v : p3.v;
            float2 f01 = __half22float2(*(__half2*)&g.x);
            float2 f23 = __half22float2(*(__half2*)&g.y);
            ax += v * f01.x; ay += v * f01.y; az += v * f23.x; aw += v * f23.y;
        }
    }
    for (; j < e; ++j) {
        Pair pp = prs[j];
        uint2 g = xh[(size_t)pp.c * 32 + lane];
        float2 f01 = __half22float2(*(__half2*)&g.x);
        float2 f23 = __half22float2(*(__half2*)&g.y);
        ax += pp.v * f01.x; ay += pp.v * f01.y; az += pp.v * f23.x; aw += pp.v * f23.y;
    }
}

// msg = spmm_p2e(ph)
__global__ void __launch_bounds__(256) spmmA_kernel(const int* __restrict__ rp,
                                                    const Pair* __restrict__ prs,
                                                    const __half* __restrict__ xh,
                                                    float* __restrict__ out) {
    int warp = (int)((blockIdx.x * (unsigned)blockDim.x + threadIdx.x) >> 5);
    if (warp >= N_EDGE) return;
    int lane = threadIdx.x & 31;
    int s = rp[warp], e = rp[warp + 1];
    float ax = 0.f, ay = 0.f, az = 0.f, aw = 0.f;
    spmm_row_acc_h(prs, (const uint2*)xh, s, e, lane, ax, ay, az, aw);
    ((float4*)out)[(size_t)warp * 32 + lane] = make_float4(ax, ay, az, aw);
}

template <int LAST>
__global__ void __launch_bounds__(256) spmmB_kernel(const int* __restrict__ rp,
                                                    const Pair* __restrict__ prs,
                                                    const __half* __restrict__ xh,
                                                    const float* __restrict__ poi,
                                                    float* __restrict__ p1,
                                                    __half* __restrict__ ph,
                                                    float* __restrict__ out) {
    int warp = (int)((blockIdx.x * (unsigned)blockDim.x + threadIdx.x) >> 5);
    if (warp >= N_POI) return;
    int lane = threadIdx.x & 31;
    int s = rp[warp], e = rp[warp + 1];
    float ax = 0.f, ay = 0.f, az = 0.f, aw = 0.f;
    spmm_row_acc_h(prs, (const uint2*)xh, s, e, lane, ax, ay, az, aw);
    size_t o = (size_t)warp * 32 + lane;
    float4 p0 = ((const float4*)poi)[o];
    if (LAST == 0) {
        float4 pn = make_float4(p0.x + ax, p0.y + ay, p0.z + az, p0.w + aw);
        ((float4*)p1)[o] = pn;
        __half2 h0 = __floats2half2_rn(pn.x, pn.y);
        __half2 h1 = __floats2half2_rn(pn.z, pn.w);
        uint2 u;
        u.x = *(unsigned*)&h0;
        u.y = *(unsigned*)&h1;
        ((uint2*)ph)[o] = u;
    } else {
        const float sc = 1.0f / 3.0f;
        float4 pv = ((const float4*)p1)[o];
        ((float4*)out)[o] = make_float4((p0.x + 2.f * pv.x + ax) * sc,
                                        (p0.y + 2.f * pv.y + ay) * sc,
                                        (p0.z + 2.f * pv.z + az) * sc,
                                        (p0.w + 2.f * pv.w + aw) * sc);
    }
}

// ---------------- edge GEMM (fp16 wmma, fp32 accumulate) + residual epilogue ----------------
// smem: phase tiles Ws (half, [128 k][MSH]) + xs (half, [128 r][MSH]); epilogue reuses
// the whole region as the fp32 C buffer [128 r][CSTR]. e_in re-read from gmem in fp32.
#define GR   128
#define MSH  136   // half-element stride, %8==0
#define CSTR 132   // float C stride, %4==0
#define SMEM_BYTES (2 * 128 * MSH * 2)   // 69632

template <int LAST>
__global__ void __launch_bounds__(256, 2) gemm2_kernel(const float* __restrict__ Wcomb,
                                                       const float* __restrict__ msg,
                                                       const float* __restrict__ e_in,
                                                       __half* __restrict__ fused_h,
                                                       float* __restrict__ e_out,
                                                       float* __restrict__ esum,
                                                       float* __restrict__ out_edge) {
    extern __shared__ __half shh[];
    __half* Ws = shh;                  // [128 k][MSH]
    __half* xs = shh + 128 * MSH;      // [128 r][MSH]
    float*  C  = (float*)shh;          // epilogue: [128 r][CSTR]
    int tid = threadIdx.x;
    int wid = tid >> 5;
    int row0 = blockIdx.x * GR;
    int warp_m = wid & 3;
    int warp_n = wid >> 2;

    wmma::fragment<wmma::accumulator, 16, 16, 16, float> acc[2][4];
#pragma unroll
    for (int m = 0; m < 2; m++)
#pragma unroll
        for (int n = 0; n < 4; n++) wmma::fill_fragment(acc[m][n], 0.f);

#pragma unroll
    for (int phase = 0; phase < 2; phase++) {
        const float* src = phase ? e_in : msg;
        int koff = phase * 128;
        if (phase) __syncthreads();
        // stage weights: Ws[k][j] = Wcomb[j][koff+k]  (fp32 -> half)
        for (int idx = tid; idx < DD * DD; idx += 256) {
            int j = idx >> 7, k = idx & 127;
            Ws[k * MSH + j] = __float2half(Wcomb[j * 256 + koff + k]);
        }
        // stage input rows fp32 -> half
        const float4* s4 = (const float4*)src;
        for (int idx = tid; idx < GR * 32; idx += 256) {
            int r = idx >> 5, k4 = idx & 31;
            int gr = row0 + r;
            float4 v = (gr < N_EDGE) ? s4[(size_t)gr * 32 + k4] : make_float4(0.f, 0.f, 0.f, 0.f);
            __half2 h0 = __floats2half2_rn(v.x, v.y);
            __half2 h1 = __floats2half2_rn(v.z, v.w);
            uint2 u;
            u.x = *(unsigned*)&h0;
            u.y = *(unsigned*)&h1;
            *(uint2*)&xs[r * MSH + k4 * 4] = u;
        }
        __syncthreads();

        for (int k0 = 0; k0 < DD; k0 += 16) {
            wmma::fragment<wmma::matrix_a, 16, 16, 16, __half, wmma::row_major> a[2];
#pragma unroll
            for (int m = 0; m < 2; m++)
                wmma::load_matrix_sync(a[m], &xs[(warp_m * 32 + m * 16) * MSH + k0], MSH);
#pragma unroll
            for (int n = 0; n < 4; n++) {
                wmma::fragment<wmma::matrix_b, 16, 16, 16, __half, wmma::row_major> b;
                wmma::load_matrix_sync(b, &Ws[k0 * MSH + warp_n * 64 + n * 16], MSH);
#pragma unroll
                for (int m = 0; m < 2; m++)
                    wmma::mma_sync(acc[m][n], a[m], b, acc[m][n]);
            }
        }
    }

    __syncthreads();   // all warps done reading Ws/xs; reuse smem as C
#pragma unroll
    for (int m = 0; m < 2; m++)
#pragma unroll
        for (int n = 0; n < 4; n++)
            wmma::store_matrix_sync(&C[(warp_m * 32 + m * 16) * CSTR + warp_n * 64 + n * 16],
                                    acc[m][n], CSTR, wmma::mem_row_major);
    __syncthreads();

    int tx = tid & 15, ty = tid >> 4;
#pragma unroll
    for (int i = 0; i < 8; i++) {
        int r = ty * 8 + i;
        int gr = row0 + r;
        if (gr >= N_EDGE) continue;
        size_t base = (size_t)gr * DD + tx * 8;
        float f[8];
#pragma unroll
        for (int j = 0; j < 8; j++) f[j] = C[r * CSTR + tx * 8 + j];
        __half2 h[4];
#pragma unroll
        for (int j = 0; j < 4; j++) h[j] = __floats2half2_rn(f[2 * j], f[2 * j + 1]);
        uint4 hv;
        hv.x = *(unsigned*)&h[0]; hv.y = *(unsigned*)&h[1];
        hv.z = *(unsigned*)&h[2]; hv.w = *(unsigned*)&h[3];
        ((uint4*)fused_h)[(size_t)gr * 16 + tx] = hv;

        // e_in rows re-read from gmem in fp32 (keeps residual state full-precision)
        float4 e0 = *(const float4*)&e_in[base];
        float4 e1v = *(const float4*)&e_in[base + 4];
        float eo[8] = {e0.x, e0.y, e0.z, e0.w, e1v.x, e1v.y, e1v.z, e1v.w};
        if (LAST == 0) {
            float en[8];
#pragma unroll
            for (int j = 0; j < 8; j++) en[j] = eo[j] + f[j];
            *(float4*)&e_out[base]     = make_float4(en[0], en[1], en[2], en[3]);
            *(float4*)&e_out[base + 4] = make_float4(en[4], en[5], en[6], en[7]);
            *(float4*)&esum[base]     = make_float4(eo[0] + en[0], eo[1] + en[1], eo[2] + en[2], eo[3] + en[3]);
            *(float4*)&esum[base + 4] = make_float4(eo[4] + en[4], eo[5] + en[5], eo[6] + en[6], eo[7] + en[7]);
        } else {
            const float sc = 1.0f / 3.0f;
            float4 s0 = *(const float4*)&esum[base];
            float4 s1 = *(const float4*)&esum[base + 4];
            *(float4*)&out_edge[base]     = make_float4((s0.x + eo[0] + f[0]) * sc, (s0.y + eo[1] + f[1]) * sc,
                                                        (s0.z + eo[2] + f[2]) * sc, (s0.w + eo[3] + f[3]) * sc);
            *(float4*)&out_edge[base + 4] = make_float4((s1.x + eo[4] + f[4]) * sc, (s1.y + eo[5] + f[5]) * sc,
                                                        (s1.z + eo[6] + f[6]) * sc, (s1.w + eo[7] + f[7]) * sc);
        }
    }
}

// ---------------- host ----------------
static void* sym_addr(const void* s) {
    void* p = nullptr;
    cudaGetSymbolAddress(&p, s);
    return p;
}

extern "C" void kernel_launch(void* const* d_in, const int* in_sizes, int n_in,
                              void* d_out, int out_size) {
    const float* poi    = (const float*)d_in[0];
    const float* edge   = (const float*)d_in[1];
    const float* Wpoi   = (const float*)d_in[2];
    const float* Wedge  = (const float*)d_in[3];
    const float* Wfus   = (const float*)d_in[4];
    const int*   p2e_r  = (const int*)d_in[5];
    const int*   p2e_c  = (const int*)d_in[6];
    const float* p2e_v  = (const float*)d_in[7];
    const int*   e2p_r  = (const int*)d_in[8];
    const int*   e2p_c  = (const int*)d_in[9];
    const float* e2p_v  = (const float*)d_in[10];
    float* out = (float*)d_out;
    float* out_edge = out + (size_t)N_POI * DD;

    float*  msg    = (float*)sym_addr(g_msg);
    float*  p1     = (float*)sym_addr(g_p1);
    float*  e1     = (float*)sym_addr(g_e1);
    float*  esum   = (float*)sym_addr(g_esum);
    __half* ph     = (__half*)sym_addr(g_ph);
    __half* fusedh = (__half*)sym_addr(g_fusedh);
    float*  Wcomb  = (float*)sym_addr(g_Wcomb);
    int*    cntA   = (int*)sym_addr(g_cntA);
    int*    cntB   = (int*)sym_addr(g_cntB);
    int*    rpA    = (int*)sym_addr(g_rpA);
    int*    rpB    = (int*)sym_addr(g_rpB);
    int*    curA   = (int*)sym_addr(g_curA);
    int*    curB   = (int*)sym_addr(g_curB);
    int*    auxA   = (int*)sym_addr(g_auxA);
    int*    auxB   = (int*)sym_addr(g_auxB);
    Pair*   prsA   = (Pair*)sym_addr(g_pairsA);
    Pair*   prsB   = (Pair*)sym_addr(g_pairsB);

    cudaFuncSetAttribute(gemm2_kernel<0>, cudaFuncAttributeMaxDynamicSharedMemorySize, SMEM_BYTES);
    cudaFuncSetAttribute(gemm2_kernel<1>, cudaFuncAttributeMaxDynamicSharedMemorySize, SMEM_BYTES);

    const int buildGrid = (2 * NNZ + 4 * 256 - 1) / (4 * 256);

    // CSR build (sub-bucketed counting sort, hierarchical scan)
    init_kernel<<<4096, 256>>>(cntA, SUB * N_EDGE, cntB, SUB * N_POI,
                               (const float4*)poi, (uint2*)ph, N_POI * 32);
    hist2_kernel<<<buildGrid, 256>>>(p2e_r, e2p_r, cntA, cntB);
    rowsum_kernel<<<512, 256>>>((const int4*)cntA, (const int4*)cntB, rpA, rpB);
    scan_blocks_kernel<<<NBLK_A + NBLK_B, 1024>>>(rpA, auxA, rpB, auxB);
    scan_aux_kernel<<<1, 64>>>(auxA, rpA, auxB, rpB);
    cursor_kernel<<<512, 256>>>(rpA, auxA, (const int4*)cntA, (int4*)curA,
                                rpB, auxB, (const int4*)cntB, (int4*)curB);
    scatter2_kernel<<<buildGrid, 256>>>(p2e_r, p2e_c, p2e_v, curA, prsA,
                                        e2p_r, e2p_c, e2p_v, curB, prsB);

    wfold_kernel<<<DD, 256>>>(Wfus, Wpoi, Wedge, Wcomb);

    const int gemmBlocks = (N_EDGE + GR - 1) / GR;

    // layer 1
    spmmA_kernel<<<(N_EDGE + 7) / 8, 256>>>(rpA, prsA, ph, msg);
    gemm2_kernel<0><<<gemmBlocks, 256, SMEM_BYTES>>>(Wcomb, msg, edge, fusedh, e1, esum, nullptr);
    spmmB_kernel<0><<<(N_POI + 7) / 8, 256>>>(rpB, prsB, fusedh, poi, p1, ph, nullptr);

    // layer 2 (last)
    spmmA_kernel<<<(N_EDGE + 7) / 8, 256>>>(rpA, prsA, ph, msg);
    gemm2_kernel<1><<<gemmBlocks, 256, SMEM_BYTES>>>(Wcomb, msg, e1, fusedh, nullptr, esum, out_edge);
    spmmB_kernel<1><<<(N_POI + 7) / 8, 256>>>(rpB, prsB, fusedh, poi, p1, nullptr, out);
}

// round 17
// speedup vs baseline: 1.3622x; 1.3622x over previous
#include <cuda_runtime.h>
#include <cuda_fp16.h>
#include <mma.h>

using namespace nvcuda;

#define N_POI  100000
#define N_EDGE 50000
#define NNZ    3200000
#define DD     128
#define SUB    16

#define SCAN_ELEMS 2048
#define NBLK_A ((N_EDGE + SCAN_ELEMS - 1) / SCAN_ELEMS)   // 25
#define NBLK_B ((N_POI  + SCAN_ELEMS - 1) / SCAN_ELEMS)   // 49

struct Pair { int c; float v; };

// ---------------- static scratch ----------------
__device__ float g_msg [(size_t)N_EDGE * DD];
__device__ float g_p1  [(size_t)N_POI * DD];
__device__ float g_e1  [(size_t)N_EDGE * DD];
__device__ float g_esum[(size_t)N_EDGE * DD];
__device__ __half g_ph    [(size_t)N_POI * DD];
__device__ __half g_fusedh[(size_t)N_EDGE * DD];
__device__ float g_Wcomb[DD * 256];

__device__ int  g_cntA[SUB * N_EDGE];
__device__ int  g_cntB[SUB * N_POI];
__device__ int  g_rpA [N_EDGE + 1];
__device__ int  g_rpB [N_POI + 1];
__device__ int  g_curA[SUB * N_EDGE];
__device__ int  g_curB[SUB * N_POI];
__device__ int  g_auxA[NBLK_A];
__device__ int  g_auxB[NBLK_B];
__device__ Pair g_pairsA[NNZ];
__device__ Pair g_pairsB[NNZ];

// ---------------- init: clear counters + poi fp32->fp16 (fused) ----------------
__global__ void init_kernel(int* __restrict__ cA, int nA, int* __restrict__ cB, int nB,
                            const float4* __restrict__ x, uint2* __restrict__ xh, int n4) {
    int total = nA + nB + n4;
    for (int i = blockIdx.x * blockDim.x + threadIdx.x; i < total; i += gridDim.x * blockDim.x) {
        if (i < nA) {
            cA[i] = 0;
        } else if (i < nA + nB) {
            cB[i - nA] = 0;
        } else {
            int k = i - nA - nB;
            float4 v = x[k];
            __half2 h0 = __floats2half2_rn(v.x, v.y);
            __half2 h1 = __floats2half2_rn(v.z, v.w);
            uint2 u;
            u.x = *(unsigned*)&h0;
            u.y = *(unsigned*)&h1;
            xh[k] = u;
        }
    }
}

// ---------------- CSR build ----------------
__global__ void __launch_bounds__(256) hist2_kernel(const int* __restrict__ rA, const int* __restrict__ rB,
                                                    int* __restrict__ cA, int* __restrict__ cB) {
    const int total = 2 * NNZ;
    const int S = gridDim.x * blockDim.x;
    int base = blockIdx.x * blockDim.x + threadIdx.x;
    int sub = base & (SUB - 1);
    for (; base < total; base += 4 * S) {
        int r[4]; bool m[4]; bool isA[4];
#pragma unroll
        for (int j = 0; j < 4; j++) {
            int i = base + j * S;
            m[j] = i < total;
            isA[j] = i < NNZ;
            if (m[j]) r[j] = isA[j] ? rA[i] : rB[i - NNZ];
        }
#pragma unroll
        for (int j = 0; j < 4; j++) {
            if (m[j]) {
                if (isA[j]) atomicAdd(&cA[r[j] * SUB + sub], 1);
                else        atomicAdd(&cB[r[j] * SUB + sub], 1);
            }
        }
    }
}

// row totals -> rp arrays (pre-scan). cnt as int4: row r = indices [r*4, r*4+4)
__global__ void rowsum_kernel(const int4* __restrict__ cntA, const int4* __restrict__ cntB,
                              int* __restrict__ rpA, int* __restrict__ rpB) {
    const int total = N_EDGE + N_POI;
    for (int r = blockIdx.x * blockDim.x + threadIdx.x; r < total; r += gridDim.x * blockDim.x) {
        const int4* cnt; int* rp; int rr;
        if (r < N_EDGE) { cnt = cntA; rp = rpA; rr = r; }
        else            { cnt = cntB; rp = rpB; rr = r - N_EDGE; }
        int s = 0;
#pragma unroll
        for (int q = 0; q < 4; q++) {
            int4 a = cnt[rr * 4 + q];
            s += a.x + a.y + a.z + a.w;
        }
        rp[rr] = s;
    }
}

// Per-block exclusive scan of 2048 elements; block total into aux.
__global__ void __launch_bounds__(1024) scan_blocks_kernel(int* __restrict__ dA, int* __restrict__ auxA,
                                                           int* __restrict__ dB, int* __restrict__ auxB) {
    __shared__ int sh[1024];
    int blk = blockIdx.x;
    int* data; int* aux; int n; int b;
    if (blk < NBLK_A) { data = dA; aux = auxA; n = N_EDGE; b = blk; }
    else              { data = dB; aux = auxB; n = N_POI;  b = blk - NBLK_A; }
    int t = threadIdx.x;
    int i0 = b * SCAN_ELEMS + t * 2;
    int x0 = (i0     < n) ? data[i0]     : 0;
    int x1 = (i0 + 1 < n) ? data[i0 + 1] : 0;
    int s = x0 + x1;
    sh[t] = s;
    __syncthreads();
#pragma unroll
    for (int off = 1; off < 1024; off <<= 1) {
        int v  = sh[t];
        int vo = (t >= off) ? sh[t - off] : 0;
        __syncthreads();
        sh[t] = v + vo;
        __syncthreads();
    }
    int excl = sh[t] - s;
    if (i0     < n) data[i0]     = excl;
    if (i0 + 1 < n) data[i0 + 1] = excl + x0;
    if (t == 1023) aux[b] = sh[1023];
}

// One block: warp 0 scans auxA, warp 1 scans auxB; writes totals to rp[n].
__global__ void scan_aux_kernel(int* __restrict__ auxA, int* __restrict__ rpA,
                                int* __restrict__ auxB, int* __restrict__ rpB) {
    int w = threadIdx.x >> 5;
    int lane = threadIdx.x & 31;
    int* aux; int nblk; int* rpEnd;
    if (w == 0) { aux = auxA; nblk = NBLK_A; rpEnd = rpA + N_EDGE; }
    else        { aux = auxB; nblk = NBLK_B; rpEnd = rpB + N_POI; }
    int carry = 0;
    for (int c = 0; c < nblk; c += 32) {
        int idx = c + lane;
        int orig = (idx < nblk) ? aux[idx] : 0;
        int v = orig;
#pragma unroll
        for (int off = 1; off < 32; off <<= 1) {
            int tmp = __shfl_up_sync(0xFFFFFFFF, v, off);
            if (lane >= off) v += tmp;
        }
        if (idx < nblk) aux[idx] = v - orig + carry;
        carry += __shfl_sync(0xFFFFFFFF, v, 31);
    }
    if (lane == 0) *rpEnd = carry;
}

// cursors: absolute base per row; 16 sub-bucket cursors per row.
__global__ void cursor_kernel(int* __restrict__ rpA, const int* __restrict__ auxA,
                              const int4* __restrict__ cntA, int4* __restrict__ curA,
                              int* __restrict__ rpB, const int* __restrict__ auxB,
                              const int4* __restrict__ cntB, int4* __restrict__ curB) {
    const int total = N_EDGE + N_POI;
    for (int r = blockIdx.x * blockDim.x + threadIdx.x; r < total; r += gridDim.x * blockDim.x) {
        const int4* cnt; int4* cur; int base; int rr; int* rp; const int* aux;
        if (r < N_EDGE) { rr = r; cnt = cntA; cur = curA; rp = rpA; aux = auxA; }
        else            { rr = r - N_EDGE; cnt = cntB; cur = curB; rp = rpB; aux = auxB; }
        base = rp[rr] + aux[rr >> 11];
        rp[rr] = base;
        int run = base;
#pragma unroll
        for (int q = 0; q < 4; q++) {
            int4 a = cnt[rr * 4 + q];
            int4 o;
            o.x = run; run += a.x;
            o.y = run; run += a.y;
            o.z = run; run += a.z;
            o.w = run; run += a.w;
            cur[rr * 4 + q] = o;
        }
    }
}

__global__ void __launch_bounds__(256) scatter2_kernel(const int* __restrict__ rA, const int* __restrict__ cAi,
                                                       const float* __restrict__ vAi, int* __restrict__ curA,
                                                       Pair* __restrict__ pA,
                                                       const int* __restrict__ rB, const int* __restrict__ cBi,
                                                       const float* __restrict__ vBi, int* __restrict__ curB,
                                                       Pair* __restrict__ pB) {
    const int total = 2 * NNZ;
    const int S = gridDim.x * blockDim.x;
    int base = blockIdx.x * blockDim.x + threadIdx.x;
    int sub = base & (SUB - 1);
    for (; base < total; base += 4 * S) {
        int r[4], c[4]; float v[4]; bool m[4], isA[4];
#pragma unroll
        for (int j = 0; j < 4; j++) {
            int i = base + j * S;
            m[j] = i < total;
            isA[j] = i < NNZ;
            if (m[j]) {
                if (isA[j]) { r[j] = rA[i]; c[j] = cAi[i]; v[j] = vAi[i]; }
                else        { int k = i - NNZ; r[j] = rB[k]; c[j] = cBi[k]; v[j] = vBi[k]; }
            }
        }
#pragma unroll
        for (int j = 0; j < 4; j++) {
            if (m[j]) {
                Pair pr; pr.c = c[j]; pr.v = v[j];
                if (isA[j]) { int pos = atomicAdd(&curA[r[j] * SUB + sub], 1); pA[pos] = pr; }
                else        { int pos = atomicAdd(&curB[r[j] * SUB + sub], 1); pB[pos] = pr; }
            }
        }
    }
}

// ---------------- weight folding ----------------
__global__ void wfold_kernel(const float* __restrict__ Wfus, const float* __restrict__ Wpoi,
                             const float* __restrict__ Wedge, float* __restrict__ Wcomb) {
    __shared__ float row[256];
    int j = blockIdx.x;
    int t = threadIdx.x;
    row[t] = Wfus[j * 256 + t];
    __syncthreads();
    float s = 0.f;
    if (t < 128) {
#pragma unroll 8
        for (int m = 0; m < 128; m++) s += row[m] * Wpoi[m * 128 + t];
    } else {
        int tt = t - 128;
#pragma unroll 8
        for (int k = 0; k < 128; k++) s += row[128 + k] * Wedge[k * 128 + tt];
    }
    Wcomb[j * 256 + t] = s;
}

// ---------------- SpMM core (fp16 gather) ----------------
__device__ __forceinline__ void spmm_row_acc_h(const Pair* __restrict__ prs,
                                               const uint2* __restrict__ xh,
                                               int s, int e, int lane,
                                               float& ax, float& ay, float& az, float& aw) {
    int j = s;
    for (; j + 4 <= e; j += 4) {
        Pair p0 = prs[j], p1 = prs[j + 1], p2 = prs[j + 2], p3 = prs[j + 3];
        uint2 g0 = xh[(size_t)p0.c * 32 + lane];
        uint2 g1 = xh[(size_t)p1.c * 32 + lane];
        uint2 g2 = xh[(size_t)p2.c * 32 + lane];
        uint2 g3 = xh[(size_t)p3.c * 32 + lane];
#pragma unroll
        for (int q = 0; q < 4; q++) {
            uint2 g = q == 0 ? g0 : q == 1 ? g1 : q == 2 ? g2 : g3;
            float v = q == 0 ? p0.v : q == 1 ? p1.v : q == 2 ? p2.v : p3.v;
            float2 f01 = __half22float2(*(__half2*)&g.x);
            float2 f23 = __half22float2(*(__half2*)&g.y);
            ax += v * f01.x; ay += v * f01.y; az += v * f23.x; aw += v * f23.y;
        }
    }
    for (; j < e; ++j) {
        Pair pp = prs[j];
        uint2 g = xh[(size_t)pp.c * 32 + lane];
        float2 f01 = __half22float2(*(__half2*)&g.x);
        float2 f23 = __half22float2(*(__half2*)&g.y);
        ax += pp.v * f01.x; ay += pp.v * f01.y; az += pp.v * f23.x; aw += pp.v * f23.y;
    }
}

// msg = spmm_p2e(ph)
__global__ void __launch_bounds__(256) spmmA_kernel(const int* __restrict__ rp,
                                                    const Pair* __restrict__ prs,
                                                    const __half* __restrict__ xh,
                                                    float* __restrict__ out) {
    int warp = (int)((blockIdx.x * (unsigned)blockDim.x + threadIdx.x) >> 5);
    if (warp >= N_EDGE) return;
    int lane = threadIdx.x & 31;
    int s = rp[warp], e = rp[warp + 1];
    float ax = 0.f, ay = 0.f, az = 0.f, aw = 0.f;
    spmm_row_acc_h(prs, (const uint2*)xh, s, e, lane, ax, ay, az, aw);
    ((float4*)out)[(size_t)warp * 32 + lane] = make_float4(ax, ay, az, aw);
}

template <int LAST>
__global__ void __launch_bounds__(256) spmmB_kernel(const int* __restrict__ rp,
                                                    const Pair* __restrict__ prs,
                                                    const __half* __restrict__ xh,
                                                    const float* __restrict__ poi,
                                                    float* __restrict__ p1,
                                                    __half* __restrict__ ph,
                                                    float* __restrict__ out) {
    int warp = (int)((blockIdx.x * (unsigned)blockDim.x + threadIdx.x) >> 5);
    if (warp >= N_POI) return;
    int lane = threadIdx.x & 31;
    int s = rp[warp], e = rp[warp + 1];
    float ax = 0.f, ay = 0.f, az = 0.f, aw = 0.f;
    spmm_row_acc_h(prs, (const uint2*)xh, s, e, lane, ax, ay, az, aw);
    size_t o = (size_t)warp * 32 + lane;
    float4 p0 = ((const float4*)poi)[o];
    if (LAST == 0) {
        float4 pn = make_float4(p0.x + ax, p0.y + ay, p0.z + az, p0.w + aw);
        ((float4*)p1)[o] = pn;
        __half2 h0 = __floats2half2_rn(pn.x, pn.y);
        __half2 h1 = __floats2half2_rn(pn.z, pn.w);
        uint2 u;
        u.x = *(unsigned*)&h0;
        u.y = *(unsigned*)&h1;
        ((uint2*)ph)[o] = u;
    } else {
        const float sc = 1.0f / 3.0f;
        float4 pv = ((const float4*)p1)[o];
        ((float4*)out)[o] = make_float4((p0.x + 2.f * pv.x + ax) * sc,
                                        (p0.y + 2.f * pv.y + ay) * sc,
                                        (p0.z + 2.f * pv.z + az) * sc,
                                        (p0.w + 2.f * pv.w + aw) * sc);
    }
}

// ---------------- edge GEMM (fp16 wmma, fp32 accumulate) + residual epilogue ----------------
#define GR   128
#define MSH  136   // half-element stride, %8==0
#define CSTR 132   // float C stride, %4==0
#define SMEM_BYTES (2 * 128 * MSH * 2)   // 69632

template <int LAST>
__global__ void __launch_bounds__(256, 2) gemm2_kernel(const float* __restrict__ Wcomb,
                                                       const float* __restrict__ msg,
                                                       const float* __restrict__ e_in,
                                                       __half* __restrict__ fused_h,
                                                       float* __restrict__ e_out,
                                                       float* __restrict__ esum,
                                                       float* __restrict__ out_edge) {
    extern __shared__ __half shh[];
    __half* Ws = shh;                  // [128 k][MSH]
    __half* xs = shh + 128 * MSH;      // [128 r][MSH]
    float*  C  = (float*)shh;          // epilogue: [128 r][CSTR]
    int tid = threadIdx.x;
    int wid = tid >> 5;
    int row0 = blockIdx.x * GR;
    int warp_m = wid & 3;
    int warp_n = wid >> 2;

    wmma::fragment<wmma::accumulator, 16, 16, 16, float> acc[2][4];
#pragma unroll
    for (int m = 0; m < 2; m++)
#pragma unroll
        for (int n = 0; n < 4; n++) wmma::fill_fragment(acc[m][n], 0.f);

#pragma unroll
    for (int phase = 0; phase < 2; phase++) {
        const float* src = phase ? e_in : msg;
        int koff = phase * 128;
        if (phase) __syncthreads();
        for (int idx = tid; idx < DD * DD; idx += 256) {
            int j = idx >> 7, k = idx & 127;
            Ws[k * MSH + j] = __float2half(Wcomb[j * 256 + koff + k]);
        }
        const float4* s4 = (const float4*)src;
        for (int idx = tid; idx < GR * 32; idx += 256) {
            int r = idx >> 5, k4 = idx & 31;
            int gr = row0 + r;
            float4 v = (gr < N_EDGE) ? s4[(size_t)gr * 32 + k4] : make_float4(0.f, 0.f, 0.f, 0.f);
            __half2 h0 = __floats2half2_rn(v.x, v.y);
            __half2 h1 = __floats2half2_rn(v.z, v.w);
            uint2 u;
            u.x = *(unsigned*)&h0;
            u.y = *(unsigned*)&h1;
            *(uint2*)&xs[r * MSH + k4 * 4] = u;
        }
        __syncthreads();

        for (int k0 = 0; k0 < DD; k0 += 16) {
            wmma::fragment<wmma::matrix_a, 16, 16, 16, __half, wmma::row_major> a[2];
#pragma unroll
            for (int m = 0; m < 2; m++)
                wmma::load_matrix_sync(a[m], &xs[(warp_m * 32 + m * 16) * MSH + k0], MSH);
#pragma unroll
            for (int n = 0; n < 4; n++) {
                wmma::fragment<wmma::matrix_b, 16, 16, 16, __half, wmma::row_major> b;
                wmma::load_matrix_sync(b, &Ws[k0 * MSH + warp_n * 64 + n * 16], MSH);
#pragma unroll
                for (int m = 0; m < 2; m++)
                    wmma::mma_sync(acc[m][n], a[m], b, acc[m][n]);
            }
        }
    }

    __syncthreads();   // all warps done reading Ws/xs; reuse smem as C
#pragma unroll
    for (int m = 0; m < 2; m++)
#pragma unroll
        for (int n = 0; n < 4; n++)
            wmma::store_matrix_sync(&C[(warp_m * 32 + m * 16) * CSTR + warp_n * 64 + n * 16],
                                    acc[m][n], CSTR, wmma::mem_row_major);
    __syncthreads();

    int tx = tid & 15, ty = tid >> 4;
#pragma unroll
    for (int i = 0; i < 8; i++) {
        int r = ty * 8 + i;
        int gr = row0 + r;
        if (gr >= N_EDGE) continue;
        size_t base = (size_t)gr * DD + tx * 8;
        float f[8];
#pragma unroll
        for (int j = 0; j < 8; j++) f[j] = C[r * CSTR + tx * 8 + j];
        __half2 h[4];
#pragma unroll
        for (int j = 0; j < 4; j++) h[j] = __floats2half2_rn(f[2 * j], f[2 * j + 1]);
        uint4 hv;
        hv.x = *(unsigned*)&h[0]; hv.y = *(unsigned*)&h[1];
        hv.z = *(unsigned*)&h[2]; hv.w = *(unsigned*)&h[3];
        ((uint4*)fused_h)[(size_t)gr * 16 + tx] = hv;

        float4 e0 = *(const float4*)&e_in[base];
        float4 e1v = *(const float4*)&e_in[base + 4];
        float eo[8] = {e0.x, e0.y, e0.z, e0.w, e1v.x, e1v.y, e1v.z, e1v.w};
        if (LAST == 0) {
            float en[8];
#pragma unroll
            for (int j = 0; j < 8; j++) en[j] = eo[j] + f[j];
            *(float4*)&e_out[base]     = make_float4(en[0], en[1], en[2], en[3]);
            *(float4*)&e_out[base + 4] = make_float4(en[4], en[5], en[6], en[7]);
            *(float4*)&esum[base]     = make_float4(eo[0] + en[0], eo[1] + en[1], eo[2] + en[2], eo[3] + en[3]);
            *(float4*)&esum[base + 4] = make_float4(eo[4] + en[4], eo[5] + en[5], eo[6] + en[6], eo[7] + en[7]);
        } else {
            const float sc = 1.0f / 3.0f;
            float4 s0 = *(const float4*)&esum[base];
            float4 s1 = *(const float4*)&esum[base + 4];
            *(float4*)&out_edge[base]     = make_float4((s0.x + eo[0] + f[0]) * sc, (s0.y + eo[1] + f[1]) * sc,
                                                        (s0.z + eo[2] + f[2]) * sc, (s0.w + eo[3] + f[3]) * sc);
            *(float4*)&out_edge[base + 4] = make_float4((s1.x + eo[4] + f[4]) * sc, (s1.y + eo[5] + f[5]) * sc,
                                                        (s1.z + eo[6] + f[6]) * sc, (s1.w + eo[7] + f[7]) * sc);
        }
    }
}

// ---------------- host ----------------
static void* sym_addr(const void* s) {
    void* p = nullptr;
    cudaGetSymbolAddress(&p, s);
    return p;
}

extern "C" void kernel_launch(void* const* d_in, const int* in_sizes, int n_in,
                              void* d_out, int out_size) {
    const float* poi    = (const float*)d_in[0];
    const float* edge   = (const float*)d_in[1];
    const float* Wpoi   = (const float*)d_in[2];
    const float* Wedge  = (const float*)d_in[3];
    const float* Wfus   = (const float*)d_in[4];
    const int*   p2e_r  = (const int*)d_in[5];
    const int*   p2e_c  = (const int*)d_in[6];
    const float* p2e_v  = (const float*)d_in[7];
    const int*   e2p_r  = (const int*)d_in[8];
    const int*   e2p_c  = (const int*)d_in[9];
    const float* e2p_v  = (const float*)d_in[10];
    float* out = (float*)d_out;
    float* out_edge = out + (size_t)N_POI * DD;

    float*  msg    = (float*)sym_addr(g_msg);
    float*  p1     = (float*)sym_addr(g_p1);
    float*  e1     = (float*)sym_addr(g_e1);
    float*  esum   = (float*)sym_addr(g_esum);
    __half* ph     = (__half*)sym_addr(g_ph);
    __half* fusedh = (__half*)sym_addr(g_fusedh);
    float*  Wcomb  = (float*)sym_addr(g_Wcomb);
    int*    cntA   = (int*)sym_addr(g_cntA);
    int*    cntB   = (int*)sym_addr(g_cntB);
    int*    rpA    = (int*)sym_addr(g_rpA);
    int*    rpB    = (int*)sym_addr(g_rpB);
    int*    curA   = (int*)sym_addr(g_curA);
    int*    curB   = (int*)sym_addr(g_curB);
    int*    auxA   = (int*)sym_addr(g_auxA);
    int*    auxB   = (int*)sym_addr(g_auxB);
    Pair*   prsA   = (Pair*)sym_addr(g_pairsA);
    Pair*   prsB   = (Pair*)sym_addr(g_pairsB);

    cudaFuncSetAttribute(gemm2_kernel<0>, cudaFuncAttributeMaxDynamicSharedMemorySize, SMEM_BYTES);
    cudaFuncSetAttribute(gemm2_kernel<1>, cudaFuncAttributeMaxDynamicSharedMemorySize, SMEM_BYTES);

    const int buildGrid = (2 * NNZ + 4 * 256 - 1) / (4 * 256);

    // CSR build (16-way sub-bucketed counting sort, hierarchical scan)
    init_kernel<<<4096, 256>>>(cntA, SUB * N_EDGE, cntB, SUB * N_POI,
                               (const float4*)poi, (uint2*)ph, N_POI * 32);
    hist2_kernel<<<buildGrid, 256>>>(p2e_r, e2p_r, cntA, cntB);
    rowsum_kernel<<<512, 256>>>((const int4*)cntA, (const int4*)cntB, rpA, rpB);
    scan_blocks_kernel<<<NBLK_A + NBLK_B, 1024>>>(rpA, auxA, rpB, auxB);
    scan_aux_kernel<<<1, 64>>>(auxA, rpA, auxB, rpB);
    cursor_kernel<<<512, 256>>>(rpA, auxA, (const int4*)cntA, (int4*)curA,
                                rpB, auxB, (const int4*)cntB, (int4*)curB);
    scatter2_kernel<<<buildGrid, 256>>>(p2e_r, p2e_c, p2e_v, curA, prsA,
                                        e2p_r, e2p_c, e2p_v, curB, prsB);

    wfold_kernel<<<DD, 256>>>(Wfus, Wpoi, Wedge, Wcomb);

    const int gemmBlocks = (N_EDGE + GR - 1) / GR;

    // layer 1
    spmmA_kernel<<<(N_EDGE + 7) / 8, 256>>>(rpA, prsA, ph, msg);
    gemm2_kernel<0><<<gemmBlocks, 256, SMEM_BYTES>>>(Wcomb, msg, edge, fusedh, e1, esum, nullptr);
    spmmB_kernel<0><<<(N_POI + 7) / 8, 256>>>(rpB, prsB, fusedh, poi, p1, ph, nullptr);

    // layer 2 (last)
    spmmA_kernel<<<(N_EDGE + 7) / 8, 256>>>(rpA, prsA, ph, msg);
    gemm2_kernel<1><<<gemmBlocks, 256, SMEM_BYTES>>>(Wcomb, msg, e1, fusedh, nullptr, esum, out_edge);
    spmmB_kernel<1><<<(N_POI + 7) / 8, 256>>>(rpB, prsB, fusedh, poi, p1, nullptr, out);
}